// round 1
// baseline (speedup 1.0000x reference)
#include <cuda_runtime.h>
#include <math.h>

// Problem constants (fixed by the dataset)
#define T_TOK 2048
#define H_DIM 1024
#define I_DIM 768
#define E_NUM 8
#define K_TOP 2
#define A_TOT (T_TOK * K_TOP)   // 4096 (token, k) assignments

// ---------------------------------------------------------------------------
// Device-global scratch (allocation-free per harness rules)
// ---------------------------------------------------------------------------
__device__ int   g_count[E_NUM];
__device__ int   g_offset[E_NUM];
__device__ int   g_cursor[E_NUM];
__device__ int   g_perm[A_TOT];            // slot -> assignment id (t*K + k)
__device__ int   g_slot[A_TOT];            // assignment id -> slot
__device__ float g_act[(size_t)A_TOT * I_DIM];   // 12.6 MB
__device__ float g_eo [(size_t)A_TOT * H_DIM];   // 16.8 MB

// ---------------------------------------------------------------------------
// Routing: group (token,k) assignments by expert, contiguous slot ranges
// ---------------------------------------------------------------------------
__global__ void route_zero() {
    if (threadIdx.x < E_NUM) g_count[threadIdx.x] = 0;
}

__global__ void route_count(const int* __restrict__ topk) {
    int a = blockIdx.x * blockDim.x + threadIdx.x;
    if (a < A_TOT) atomicAdd(&g_count[topk[a]], 1);
}

__global__ void route_scan() {
    // single thread: 8-entry exclusive prefix sum
    int s = 0;
    for (int e = 0; e < E_NUM; e++) {
        g_offset[e] = s;
        g_cursor[e] = s;
        s += g_count[e];
    }
}

__global__ void route_scatter(const int* __restrict__ topk) {
    int a = blockIdx.x * blockDim.x + threadIdx.x;
    if (a < A_TOT) {
        int e = topk[a];
        int s = atomicAdd(&g_cursor[e], 1);
        g_perm[s] = a;
        g_slot[a] = s;
    }
}

// ---------------------------------------------------------------------------
// GEMM tiling config (shared by both GEMMs)
// ---------------------------------------------------------------------------
#define BM 128
#define BN 64
#define BK 8
// 256 threads; thread micro-tile 8(M) x 4(N)

// ---------------------------------------------------------------------------
// GEMM1 (fused gate/up + SiLU):
//   for expert e, rows = gathered tokens in slot range [off, off+cnt)
//   gate[m, n] = sum_h X[tok(m), h] * Wgu[e, n,        h]
//   up  [m, n] = sum_h X[tok(m), h] * Wgu[e, n + I,    h]
//   g_act[off+m, n] = silu(gate) * up
// ---------------------------------------------------------------------------
__global__ __launch_bounds__(256, 2)
void gemm1_gateup(const float* __restrict__ X, const float* __restrict__ Wgu) {
    const int e   = blockIdx.z;
    const int cnt = g_count[e];
    const int m0  = blockIdx.x * BM;
    if (m0 >= cnt) return;
    const int off = g_offset[e];
    const int n0  = blockIdx.y * BN;           // act column tile in [0, I)

    __shared__ float As[BK][BM];
    __shared__ float Bg[BK][BN];
    __shared__ float Bu[BK][BN];
    __shared__ int   rowtok[BM];

    const int tid = threadIdx.x;
    if (tid < BM) {
        int m = m0 + tid;
        rowtok[tid] = (m < cnt) ? (g_perm[off + m] / K_TOP) : -1;
    }
    __syncthreads();

    const float* Wbase = Wgu + (size_t)e * (2 * I_DIM) * H_DIM;

    float acc_g[8][4], acc_u[8][4];
    #pragma unroll
    for (int i = 0; i < 8; i++)
        #pragma unroll
        for (int j = 0; j < 4; j++) { acc_g[i][j] = 0.f; acc_u[i][j] = 0.f; }

    const int ty = tid >> 4;          // 0..15  (M)
    const int tx = tid & 15;          // 0..15  (N)

    // A-load mapping: one float4 per thread (128 rows x 2 quads)
    const int arow = tid >> 1;        // 0..127
    const int akq  = tid & 1;         // quad within BK
    // B-load mapping: tid<128 -> gate, tid>=128 -> up (64 rows x 2 quads each)
    const int brow  = (tid & 127) >> 1;   // 0..63
    const int bkq   = tid & 1;
    const bool is_up = (tid >= 128);

    for (int k0 = 0; k0 < H_DIM; k0 += BK) {
        // ---- load A tile (gathered token rows) ----
        {
            int t = rowtok[arow];
            float4 v = make_float4(0.f, 0.f, 0.f, 0.f);
            if (t >= 0)
                v = *(const float4*)(X + (size_t)t * H_DIM + k0 + akq * 4);
            As[akq * 4 + 0][arow] = v.x;
            As[akq * 4 + 1][arow] = v.y;
            As[akq * 4 + 2][arow] = v.z;
            As[akq * 4 + 3][arow] = v.w;
        }
        // ---- load B tiles (gate and up weight rows) ----
        {
            int wrow = n0 + brow + (is_up ? I_DIM : 0);
            float4 v = *(const float4*)(Wbase + (size_t)wrow * H_DIM + k0 + bkq * 4);
            if (is_up) {
                Bu[bkq * 4 + 0][brow] = v.x; Bu[bkq * 4 + 1][brow] = v.y;
                Bu[bkq * 4 + 2][brow] = v.z; Bu[bkq * 4 + 3][brow] = v.w;
            } else {
                Bg[bkq * 4 + 0][brow] = v.x; Bg[bkq * 4 + 1][brow] = v.y;
                Bg[bkq * 4 + 2][brow] = v.z; Bg[bkq * 4 + 3][brow] = v.w;
            }
        }
        __syncthreads();

        #pragma unroll
        for (int kk = 0; kk < BK; kk++) {
            float a[8], bg[4], bu[4];
            #pragma unroll
            for (int i = 0; i < 8; i++) a[i] = As[kk][ty * 8 + i];
            #pragma unroll
            for (int j = 0; j < 4; j++) { bg[j] = Bg[kk][tx * 4 + j]; bu[j] = Bu[kk][tx * 4 + j]; }
            #pragma unroll
            for (int i = 0; i < 8; i++)
                #pragma unroll
                for (int j = 0; j < 4; j++) {
                    acc_g[i][j] += a[i] * bg[j];
                    acc_u[i][j] += a[i] * bu[j];
                }
        }
        __syncthreads();
    }

    // ---- epilogue: act = silu(gate) * up ----
    #pragma unroll
    for (int i = 0; i < 8; i++) {
        int m = m0 + ty * 8 + i;
        if (m < cnt) {
            float4 r;
            #pragma unroll
            for (int j = 0; j < 4; j++) {
                float gv = acc_g[i][j];
                float uv = acc_u[i][j];
                float s  = gv / (1.f + __expf(-gv));
                ((float*)&r)[j] = s * uv;
            }
            *(float4*)(g_act + (size_t)(off + m) * I_DIM + n0 + tx * 4) = r;
        }
    }
}

// ---------------------------------------------------------------------------
// GEMM2 (down projection):
//   g_eo[off+m, h] = sum_i g_act[off+m, i] * Wd[e, h, i]
//   A rows are contiguous in slot order (no gather needed).
// ---------------------------------------------------------------------------
__global__ __launch_bounds__(256, 2)
void gemm2_down(const float* __restrict__ Wd) {
    const int e   = blockIdx.z;
    const int cnt = g_count[e];
    const int m0  = blockIdx.x * BM;
    if (m0 >= cnt) return;
    const int off = g_offset[e];
    const int n0  = blockIdx.y * BN;          // h tile in [0, H)

    __shared__ float As[BK][BM];
    __shared__ float Bs[BK][BN];

    const int tid = threadIdx.x;
    const float* Abase = g_act + (size_t)off * I_DIM;
    const float* Wbase = Wd + (size_t)e * H_DIM * I_DIM;

    float acc[8][4];
    #pragma unroll
    for (int i = 0; i < 8; i++)
        #pragma unroll
        for (int j = 0; j < 4; j++) acc[i][j] = 0.f;

    const int ty = tid >> 4;
    const int tx = tid & 15;

    const int arow = tid >> 1;      // 0..127
    const int akq  = tid & 1;
    const int brow = (tid & 127) >> 1;  // 0..63
    const int bkq  = tid & 1;
    const bool do_b = (tid < 128);

    for (int k0 = 0; k0 < I_DIM; k0 += BK) {
        {
            int m = m0 + arow;
            float4 v = make_float4(0.f, 0.f, 0.f, 0.f);
            if (m < cnt)
                v = *(const float4*)(Abase + (size_t)m * I_DIM + k0 + akq * 4);
            As[akq * 4 + 0][arow] = v.x;
            As[akq * 4 + 1][arow] = v.y;
            As[akq * 4 + 2][arow] = v.z;
            As[akq * 4 + 3][arow] = v.w;
        }
        if (do_b) {
            int h = n0 + brow;
            float4 v = *(const float4*)(Wbase + (size_t)h * I_DIM + k0 + bkq * 4);
            Bs[bkq * 4 + 0][brow] = v.x; Bs[bkq * 4 + 1][brow] = v.y;
            Bs[bkq * 4 + 2][brow] = v.z; Bs[bkq * 4 + 3][brow] = v.w;
        }
        __syncthreads();

        #pragma unroll
        for (int kk = 0; kk < BK; kk++) {
            float a[8], b[4];
            #pragma unroll
            for (int i = 0; i < 8; i++) a[i] = As[kk][ty * 8 + i];
            #pragma unroll
            for (int j = 0; j < 4; j++) b[j] = Bs[kk][tx * 4 + j];
            #pragma unroll
            for (int i = 0; i < 8; i++)
                #pragma unroll
                for (int j = 0; j < 4; j++)
                    acc[i][j] += a[i] * b[j];
        }
        __syncthreads();
    }

    #pragma unroll
    for (int i = 0; i < 8; i++) {
        int m = m0 + ty * 8 + i;
        if (m < cnt) {
            float4 r = make_float4(acc[i][0], acc[i][1], acc[i][2], acc[i][3]);
            *(float4*)(g_eo + (size_t)(off + m) * H_DIM + n0 + tx * 4) = r;
        }
    }
}

// ---------------------------------------------------------------------------
// Combine: out[t, h] = w[t,0] * eo[slot(t,0), h] + w[t,1] * eo[slot(t,1), h]
// ---------------------------------------------------------------------------
__global__ void combine(const float* __restrict__ wts, float* __restrict__ out) {
    int idx = blockIdx.x * blockDim.x + threadIdx.x;   // over T*H/4
    if (idx >= T_TOK * H_DIM / 4) return;
    int t  = idx / (H_DIM / 4);
    int h4 = idx % (H_DIM / 4);
    float w0 = wts[t * K_TOP + 0];
    float w1 = wts[t * K_TOP + 1];
    int s0 = g_slot[t * K_TOP + 0];
    int s1 = g_slot[t * K_TOP + 1];
    float4 a = ((const float4*)(g_eo + (size_t)s0 * H_DIM))[h4];
    float4 b = ((const float4*)(g_eo + (size_t)s1 * H_DIM))[h4];
    float4 r;
    r.x = w0 * a.x + w1 * b.x;
    r.y = w0 * a.y + w1 * b.y;
    r.z = w0 * a.z + w1 * b.z;
    r.w = w0 * a.w + w1 * b.w;
    ((float4*)out)[idx] = r;
}

// ---------------------------------------------------------------------------
// Launch
// ---------------------------------------------------------------------------
extern "C" void kernel_launch(void* const* d_in, const int* in_sizes, int n_in,
                              void* d_out, int out_size) {
    const float* X    = (const float*)d_in[0];   // (T, H)
    const float* Wgu  = (const float*)d_in[1];   // (E, 2I, H)
    const float* Wd   = (const float*)d_in[2];   // (E, H, I)
    const int*   topk = (const int*)  d_in[3];   // (T, K)
    const float* wts  = (const float*)d_in[4];   // (T, K)
    float*       out  = (float*)d_out;           // (T, H)

    route_zero<<<1, 32>>>();
    route_count<<<A_TOT / 256, 256>>>(topk);
    route_scan<<<1, 1>>>();
    route_scatter<<<A_TOT / 256, 256>>>(topk);

    dim3 g1(A_TOT / BM, I_DIM / BN, E_NUM);   // (32, 12, 8)
    gemm1_gateup<<<g1, 256>>>(X, Wgu);

    dim3 g2(A_TOT / BM, H_DIM / BN, E_NUM);   // (32, 16, 8)
    gemm2_down<<<g2, 256>>>(Wd);

    combine<<<(T_TOK * H_DIM / 4 + 255) / 256, 256>>>(wts, out);
}

// round 3
// speedup vs baseline: 2.2109x; 2.2109x over previous
#include <cuda_runtime.h>
#include <cuda_bf16.h>
#include <stdint.h>

// Problem constants
#define T_TOK 2048
#define H_DIM 1024
#define I_DIM 768
#define E_NUM 8
#define K_TOP 2
#define A_TOT (T_TOK * K_TOP)   // 4096

// ---------------------------------------------------------------------------
// Device-global scratch
// ---------------------------------------------------------------------------
__device__ int   g_count[E_NUM];
__device__ int   g_offset[E_NUM];
__device__ int   g_cursor[E_NUM];
__device__ int   g_perm[A_TOT];
__device__ int   g_slot[A_TOT];
__device__ float g_act[(size_t)A_TOT * I_DIM];
__device__ float g_eo [(size_t)A_TOT * H_DIM];

// ---------------------------------------------------------------------------
// MMA / ldmatrix helpers (base PTX, valid on sm_100 target)
// ---------------------------------------------------------------------------
__device__ __forceinline__ uint32_t smem_u32(const void* p) {
    uint32_t a;
    asm("{ .reg .u64 t; cvta.to.shared.u64 t, %1; cvt.u32.u64 %0, t; }" : "=r"(a) : "l"(p));
    return a;
}

#define LDSM_X4(R0, R1, R2, R3, ADDR) \
    asm volatile("ldmatrix.sync.aligned.m8n8.x4.shared.b16 {%0,%1,%2,%3}, [%4];" \
        : "=r"(R0), "=r"(R1), "=r"(R2), "=r"(R3) : "r"(ADDR))

#define MMA_BF16(D, A, B0, B1) \
    asm volatile("mma.sync.aligned.m16n8k16.row.col.f32.bf16.bf16.f32 " \
        "{%0,%1,%2,%3}, {%4,%5,%6,%7}, {%8,%9}, {%0,%1,%2,%3};" \
        : "+f"((D)[0]), "+f"((D)[1]), "+f"((D)[2]), "+f"((D)[3]) \
        : "r"((A)[0]), "r"((A)[1]), "r"((A)[2]), "r"((A)[3]), "r"(B0), "r"(B1))

// fp32x4 -> bf16 hi/lo packed pairs
__device__ __forceinline__ void split4(float4 v, uint2& uh, uint2& ul) {
    __nv_bfloat16 h0 = __float2bfloat16(v.x), h1 = __float2bfloat16(v.y);
    __nv_bfloat16 h2 = __float2bfloat16(v.z), h3 = __float2bfloat16(v.w);
    __nv_bfloat16 l0 = __float2bfloat16(v.x - __bfloat162float(h0));
    __nv_bfloat16 l1 = __float2bfloat16(v.y - __bfloat162float(h1));
    __nv_bfloat16 l2 = __float2bfloat16(v.z - __bfloat162float(h2));
    __nv_bfloat16 l3 = __float2bfloat16(v.w - __bfloat162float(h3));
    uh.x = (uint32_t)__bfloat16_as_ushort(h0) | ((uint32_t)__bfloat16_as_ushort(h1) << 16);
    uh.y = (uint32_t)__bfloat16_as_ushort(h2) | ((uint32_t)__bfloat16_as_ushort(h3) << 16);
    ul.x = (uint32_t)__bfloat16_as_ushort(l0) | ((uint32_t)__bfloat16_as_ushort(l1) << 16);
    ul.y = (uint32_t)__bfloat16_as_ushort(l2) | ((uint32_t)__bfloat16_as_ushort(l3) << 16);
}

// ---------------------------------------------------------------------------
// SMEM layout (elements of bf16): padded stride avoids ldmatrix conflicts
// ---------------------------------------------------------------------------
#define KC      32
#define STRIDE  40                    // 32 cols + 8 pad (80B rows)
#define TILE_E  (128 * STRIDE)        // 5120 elems per matrix
#define STAGE_E (4 * TILE_E)          // Ah | Al | Bh | Bl
#define SMEM_BYTES (2 * STAGE_E * 2)  // 2 stages * bf16 = 81920

// ---------------------------------------------------------------------------
// Routing
// ---------------------------------------------------------------------------
__global__ void route_zero() { if (threadIdx.x < E_NUM) g_count[threadIdx.x] = 0; }
__global__ void route_count(const int* __restrict__ topk) {
    int a = blockIdx.x * blockDim.x + threadIdx.x;
    if (a < A_TOT) atomicAdd(&g_count[topk[a]], 1);
}
__global__ void route_scan() {
    int s = 0;
    for (int e = 0; e < E_NUM; e++) { g_offset[e] = s; g_cursor[e] = s; s += g_count[e]; }
}
__global__ void route_scatter(const int* __restrict__ topk) {
    int a = blockIdx.x * blockDim.x + threadIdx.x;
    if (a < A_TOT) {
        int e = topk[a];
        int s = atomicAdd(&g_cursor[e], 1);
        g_perm[s] = a;
        g_slot[a] = s;
    }
}

// ---------------------------------------------------------------------------
// Fragment loaders
// ---------------------------------------------------------------------------
// A-frag (m16k16, row-major in smem): lanes 0-15 -> &A[lane][0], 16-31 -> &A[lane-16][8]
__device__ __forceinline__ void load_afrag(uint32_t sb, int eoff, int row0, int kk,
                                           int lane, uint32_t a[4]) {
    int row = row0 + (lane & 15);
    int col = kk + ((lane >> 4) << 3);
    uint32_t addr = sb + (uint32_t)(eoff + row * STRIDE + col) * 2;
    LDSM_X4(a[0], a[1], a[2], a[3], addr);
}
// B-frag x4 covering two n8 tiles: lanes map (n_sub, k_half) = ((lane>>4)&1, (lane>>3)&1)
__device__ __forceinline__ void load_bfrag(uint32_t sb, int eoff, int nbase, int kk,
                                           int lane, uint32_t b[4]) {
    int row = nbase + (((lane >> 4) & 1) << 3) + (lane & 7);
    int col = kk + (((lane >> 3) & 1) << 3);
    uint32_t addr = sb + (uint32_t)(eoff + row * STRIDE + col) * 2;
    LDSM_X4(b[0], b[1], b[2], b[3], addr);
}

// ---------------------------------------------------------------------------
// GEMM1: act = silu(X*Wg^T) * (X*Wu^T).  Block: 128 slots x 64 gate cols (+64 up).
// B tile rows 0-63 = gate rows n0g+r, rows 64-127 = up rows I+n0g+(r-64).
// ---------------------------------------------------------------------------
#define NCH1 (H_DIM / KC)   // 32 chunks

__global__ __launch_bounds__(256, 1)
void gemm1(const float* __restrict__ X, const float* __restrict__ Wgu) {
    const int e   = blockIdx.z;
    const int cnt = g_count[e];
    const int m0  = blockIdx.x * 128;
    if (m0 >= cnt) return;
    const int off  = g_offset[e];
    const int n0g  = blockIdx.y * 64;
    const int cntm = cnt - m0;           // valid rows in this tile

    extern __shared__ __nv_bfloat16 smem[];
    __shared__ int rowtok[128];
    const uint32_t sb = smem_u32(smem);

    const int tid = threadIdx.x, lane = tid & 31, wid = tid >> 5;
    const int wm = wid & 3, wn = wid >> 2;

    if (tid < 128) {
        rowtok[tid] = (tid < cntm) ? g_perm[off + m0 + tid] / K_TOP : -1;
    }
    __syncthreads();

    const float* Wb = Wgu + (size_t)e * (2 * I_DIM) * H_DIM;

    const int lrow = tid >> 3;           // 0..31 per 256.. (idx>>3 below)
    (void)lrow;

    float accG[2][4][4], accU[2][4][4];
    #pragma unroll
    for (int a = 0; a < 2; a++)
        #pragma unroll
        for (int b = 0; b < 4; b++)
            #pragma unroll
            for (int c = 0; c < 4; c++) { accG[a][b][c] = 0.f; accU[a][b][c] = 0.f; }

    // ---- prologue: chunk 0 -> stage 0 ----
    {
        const int k0 = 0;
        #pragma unroll
        for (int i = 0; i < 4; i++) {
            int idx = tid + i * 256;
            int row = idx >> 3, c4 = idx & 7;
            int tok = rowtok[row];
            float4 va = make_float4(0.f, 0.f, 0.f, 0.f);
            if (tok >= 0) va = *(const float4*)(X + (size_t)tok * H_DIM + k0 + c4 * 4);
            int wr = (row < 64) ? (n0g + row) : (I_DIM + n0g + row - 64);
            float4 vb = *(const float4*)(Wb + (size_t)wr * H_DIM + k0 + c4 * 4);
            uint2 uh, ul;
            int eo = row * STRIDE + c4 * 4;
            split4(va, uh, ul);
            *(uint2*)((char*)smem + (0 * TILE_E + eo) * 2) = uh;   // Ah
            *(uint2*)((char*)smem + (1 * TILE_E + eo) * 2) = ul;   // Al
            split4(vb, uh, ul);
            *(uint2*)((char*)smem + (2 * TILE_E + eo) * 2) = uh;   // Bh
            *(uint2*)((char*)smem + (3 * TILE_E + eo) * 2) = ul;   // Bl
        }
    }
    __syncthreads();

    for (int c = 0; c < NCH1; c++) {
        const int s = c & 1;
        // prefetch next chunk into registers
        float4 av[4], bv[4];
        if (c + 1 < NCH1) {
            const int k0 = (c + 1) * KC;
            #pragma unroll
            for (int i = 0; i < 4; i++) {
                int idx = tid + i * 256;
                int row = idx >> 3, c4 = idx & 7;
                int tok = rowtok[row];
                av[i] = make_float4(0.f, 0.f, 0.f, 0.f);
                if (tok >= 0) av[i] = *(const float4*)(X + (size_t)tok * H_DIM + k0 + c4 * 4);
                int wr = (row < 64) ? (n0g + row) : (I_DIM + n0g + row - 64);
                bv[i] = *(const float4*)(Wb + (size_t)wr * H_DIM + k0 + c4 * 4);
            }
        }
        // compute on stage s
        {
            const int so = s * STAGE_E;
            #pragma unroll
            for (int kk = 0; kk < KC; kk += 16) {
                uint32_t ah[2][4], al[2][4];
                #pragma unroll
                for (int mt = 0; mt < 2; mt++) {
                    load_afrag(sb, so + 0 * TILE_E, wm * 32 + mt * 16, kk, lane, ah[mt]);
                    load_afrag(sb, so + 1 * TILE_E, wm * 32 + mt * 16, kk, lane, al[mt]);
                }
                #pragma unroll
                for (int p = 0; p < 2; p++) {
                    const int nbg = wn * 32 + p * 16;       // gate rows
                    uint32_t bgh[4], bgl[4], buh[4], bul[4];
                    load_bfrag(sb, so + 2 * TILE_E, nbg,      kk, lane, bgh);
                    load_bfrag(sb, so + 3 * TILE_E, nbg,      kk, lane, bgl);
                    load_bfrag(sb, so + 2 * TILE_E, nbg + 64, kk, lane, buh);
                    load_bfrag(sb, so + 3 * TILE_E, nbg + 64, kk, lane, bul);
                    #pragma unroll
                    for (int mt = 0; mt < 2; mt++) {
                        #pragma unroll
                        for (int q = 0; q < 2; q++) {
                            float* dG = accG[mt][2 * p + q];
                            float* dU = accU[mt][2 * p + q];
                            MMA_BF16(dG, ah[mt], bgh[2 * q], bgh[2 * q + 1]);
                            MMA_BF16(dG, ah[mt], bgl[2 * q], bgl[2 * q + 1]);
                            MMA_BF16(dG, al[mt], bgh[2 * q], bgh[2 * q + 1]);
                            MMA_BF16(dU, ah[mt], buh[2 * q], buh[2 * q + 1]);
                            MMA_BF16(dU, ah[mt], bul[2 * q], bul[2 * q + 1]);
                            MMA_BF16(dU, al[mt], buh[2 * q], buh[2 * q + 1]);
                        }
                    }
                }
            }
        }
        // store prefetched chunk to the other stage
        if (c + 1 < NCH1) {
            const int so = (s ^ 1) * STAGE_E;
            #pragma unroll
            for (int i = 0; i < 4; i++) {
                int idx = tid + i * 256;
                int row = idx >> 3, c4 = idx & 7;
                int eo = row * STRIDE + c4 * 4;
                uint2 uh, ul;
                split4(av[i], uh, ul);
                *(uint2*)((char*)smem + (so + 0 * TILE_E + eo) * 2) = uh;
                *(uint2*)((char*)smem + (so + 1 * TILE_E + eo) * 2) = ul;
                split4(bv[i], uh, ul);
                *(uint2*)((char*)smem + (so + 2 * TILE_E + eo) * 2) = uh;
                *(uint2*)((char*)smem + (so + 3 * TILE_E + eo) * 2) = ul;
            }
        }
        __syncthreads();
    }

    // ---- epilogue: silu(gate) * up -> g_act ----
    const int gid = lane >> 2, tig = lane & 3;
    #pragma unroll
    for (int mt = 0; mt < 2; mt++) {
        #pragma unroll
        for (int nt = 0; nt < 4; nt++) {
            int colg = n0g + wn * 32 + nt * 8 + 2 * tig;
            #pragma unroll
            for (int h = 0; h < 2; h++) {                 // c01 (row) / c23 (row+8)
                int rowl = wm * 32 + mt * 16 + gid + h * 8;
                if (rowl < cntm) {
                    float g0 = accG[mt][nt][2 * h],     u0 = accU[mt][nt][2 * h];
                    float g1 = accG[mt][nt][2 * h + 1], u1 = accU[mt][nt][2 * h + 1];
                    float2 r;
                    r.x = (g0 / (1.f + __expf(-g0))) * u0;
                    r.y = (g1 / (1.f + __expf(-g1))) * u1;
                    *(float2*)(g_act + (size_t)(off + m0 + rowl) * I_DIM + colg) = r;
                }
            }
        }
    }
}

// ---------------------------------------------------------------------------
// GEMM2: eo = act * Wd^T.  Block: 128 slots x 128 H cols, K=768.
// ---------------------------------------------------------------------------
#define NCH2 (I_DIM / KC)   // 24 chunks

__global__ __launch_bounds__(256, 1)
void gemm2(const float* __restrict__ Wd) {
    const int e   = blockIdx.z;
    const int cnt = g_count[e];
    const int m0  = blockIdx.x * 128;
    if (m0 >= cnt) return;
    const int off  = g_offset[e];
    const int n0   = blockIdx.y * 128;
    const int cntm = cnt - m0;

    extern __shared__ __nv_bfloat16 smem[];
    const uint32_t sb = smem_u32(smem);

    const int tid = threadIdx.x, lane = tid & 31, wid = tid >> 5;
    const int wm = wid & 3, wn = wid >> 2;

    const float* Ab = g_act + (size_t)off * I_DIM;
    const float* Wb = Wd + (size_t)e * H_DIM * I_DIM;

    float acc[2][8][4];
    #pragma unroll
    for (int a = 0; a < 2; a++)
        #pragma unroll
        for (int b = 0; b < 8; b++)
            #pragma unroll
            for (int c = 0; c < 4; c++) acc[a][b][c] = 0.f;

    // prologue
    {
        const int k0 = 0;
        #pragma unroll
        for (int i = 0; i < 4; i++) {
            int idx = tid + i * 256;
            int row = idx >> 3, c4 = idx & 7;
            float4 va = make_float4(0.f, 0.f, 0.f, 0.f);
            if (row < cntm) va = *(const float4*)(Ab + (size_t)(m0 + row) * I_DIM + k0 + c4 * 4);
            float4 vb = *(const float4*)(Wb + (size_t)(n0 + row) * I_DIM + k0 + c4 * 4);
            uint2 uh, ul;
            int eo = row * STRIDE + c4 * 4;
            split4(va, uh, ul);
            *(uint2*)((char*)smem + (0 * TILE_E + eo) * 2) = uh;
            *(uint2*)((char*)smem + (1 * TILE_E + eo) * 2) = ul;
            split4(vb, uh, ul);
            *(uint2*)((char*)smem + (2 * TILE_E + eo) * 2) = uh;
            *(uint2*)((char*)smem + (3 * TILE_E + eo) * 2) = ul;
        }
    }
    __syncthreads();

    for (int c = 0; c < NCH2; c++) {
        const int s = c & 1;
        float4 av[4], bv[4];
        if (c + 1 < NCH2) {
            const int k0 = (c + 1) * KC;
            #pragma unroll
            for (int i = 0; i < 4; i++) {
                int idx = tid + i * 256;
                int row = idx >> 3, c4 = idx & 7;
                av[i] = make_float4(0.f, 0.f, 0.f, 0.f);
                if (row < cntm) av[i] = *(const float4*)(Ab + (size_t)(m0 + row) * I_DIM + k0 + c4 * 4);
                bv[i] = *(const float4*)(Wb + (size_t)(n0 + row) * I_DIM + k0 + c4 * 4);
            }
        }
        {
            const int so = s * STAGE_E;
            #pragma unroll
            for (int kk = 0; kk < KC; kk += 16) {
                uint32_t ah[2][4], al[2][4];
                #pragma unroll
                for (int mt = 0; mt < 2; mt++) {
                    load_afrag(sb, so + 0 * TILE_E, wm * 32 + mt * 16, kk, lane, ah[mt]);
                    load_afrag(sb, so + 1 * TILE_E, wm * 32 + mt * 16, kk, lane, al[mt]);
                }
                #pragma unroll
                for (int p = 0; p < 4; p++) {
                    const int nb = wn * 64 + p * 16;
                    uint32_t bh[4], bl[4];
                    load_bfrag(sb, so + 2 * TILE_E, nb, kk, lane, bh);
                    load_bfrag(sb, so + 3 * TILE_E, nb, kk, lane, bl);
                    #pragma unroll
                    for (int mt = 0; mt < 2; mt++) {
                        #pragma unroll
                        for (int q = 0; q < 2; q++) {
                            float* d = acc[mt][2 * p + q];
                            MMA_BF16(d, ah[mt], bh[2 * q], bh[2 * q + 1]);
                            MMA_BF16(d, ah[mt], bl[2 * q], bl[2 * q + 1]);
                            MMA_BF16(d, al[mt], bh[2 * q], bh[2 * q + 1]);
                        }
                    }
                }
            }
        }
        if (c + 1 < NCH2) {
            const int so = (s ^ 1) * STAGE_E;
            #pragma unroll
            for (int i = 0; i < 4; i++) {
                int idx = tid + i * 256;
                int row = idx >> 3, c4 = idx & 7;
                int eo = row * STRIDE + c4 * 4;
                uint2 uh, ul;
                split4(av[i], uh, ul);
                *(uint2*)((char*)smem + (so + 0 * TILE_E + eo) * 2) = uh;
                *(uint2*)((char*)smem + (so + 1 * TILE_E + eo) * 2) = ul;
                split4(bv[i], uh, ul);
                *(uint2*)((char*)smem + (so + 2 * TILE_E + eo) * 2) = uh;
                *(uint2*)((char*)smem + (so + 3 * TILE_E + eo) * 2) = ul;
            }
        }
        __syncthreads();
    }

    // epilogue
    const int gid = lane >> 2, tig = lane & 3;
    #pragma unroll
    for (int mt = 0; mt < 2; mt++) {
        #pragma unroll
        for (int nt = 0; nt < 8; nt++) {
            int col = n0 + wn * 64 + nt * 8 + 2 * tig;
            #pragma unroll
            for (int h = 0; h < 2; h++) {
                int rowl = wm * 32 + mt * 16 + gid + h * 8;
                if (rowl < cntm) {
                    float2 r = make_float2(acc[mt][nt][2 * h], acc[mt][nt][2 * h + 1]);
                    *(float2*)(g_eo + (size_t)(off + m0 + rowl) * H_DIM + col) = r;
                }
            }
        }
    }
}

// ---------------------------------------------------------------------------
// Combine
// ---------------------------------------------------------------------------
__global__ void combine(const float* __restrict__ wts, float* __restrict__ out) {
    int idx = blockIdx.x * blockDim.x + threadIdx.x;
    if (idx >= T_TOK * H_DIM / 4) return;
    int t  = idx / (H_DIM / 4);
    int h4 = idx % (H_DIM / 4);
    float w0 = wts[t * K_TOP + 0];
    float w1 = wts[t * K_TOP + 1];
    int s0 = g_slot[t * K_TOP + 0];
    int s1 = g_slot[t * K_TOP + 1];
    float4 a = ((const float4*)(g_eo + (size_t)s0 * H_DIM))[h4];
    float4 b = ((const float4*)(g_eo + (size_t)s1 * H_DIM))[h4];
    float4 r;
    r.x = w0 * a.x + w1 * b.x;
    r.y = w0 * a.y + w1 * b.y;
    r.z = w0 * a.z + w1 * b.z;
    r.w = w0 * a.w + w1 * b.w;
    ((float4*)out)[idx] = r;
}

// ---------------------------------------------------------------------------
// Launch
// ---------------------------------------------------------------------------
extern "C" void kernel_launch(void* const* d_in, const int* in_sizes, int n_in,
                              void* d_out, int out_size) {
    const float* X    = (const float*)d_in[0];
    const float* Wgu  = (const float*)d_in[1];
    const float* Wd   = (const float*)d_in[2];
    const int*   topk = (const int*)  d_in[3];
    const float* wts  = (const float*)d_in[4];
    float*       out  = (float*)d_out;

    static bool attr_set = false;
    if (!attr_set) {
        cudaFuncSetAttribute(gemm1, cudaFuncAttributeMaxDynamicSharedMemorySize, SMEM_BYTES);
        cudaFuncSetAttribute(gemm2, cudaFuncAttributeMaxDynamicSharedMemorySize, SMEM_BYTES);
        attr_set = true;
    }

    route_zero<<<1, 32>>>();
    route_count<<<A_TOT / 256, 256>>>(topk);
    route_scan<<<1, 1>>>();
    route_scatter<<<A_TOT / 256, 256>>>(topk);

    dim3 g1(A_TOT / 128, I_DIM / 64, E_NUM);    // (32, 12, 8)
    gemm1<<<g1, 256, SMEM_BYTES>>>(X, Wgu);

    dim3 g2(A_TOT / 128, H_DIM / 128, E_NUM);   // (32, 8, 8)
    gemm2<<<g2, 256, SMEM_BYTES>>>(Wd);

    combine<<<(T_TOK * H_DIM / 4 + 255) / 256, 256>>>(wts, out);
}

// round 4
// speedup vs baseline: 2.6576x; 1.2020x over previous
#include <cuda_runtime.h>
#include <cuda_bf16.h>
#include <stdint.h>

// Problem constants
#define T_TOK 2048
#define H_DIM 1024
#define I_DIM 768
#define E_NUM 8
#define K_TOP 2
#define A_TOT (T_TOK * K_TOP)   // 4096

// ---------------------------------------------------------------------------
// Device-global scratch (pre-split bf16 hi/lo copies + routing + outputs)
// ---------------------------------------------------------------------------
__device__ int   g_count[E_NUM];
__device__ int   g_offset[E_NUM];
__device__ int   g_perm[A_TOT];
__device__ int   g_slot[A_TOT];
__device__ __nv_bfloat16 g_xh[(size_t)T_TOK * H_DIM];
__device__ __nv_bfloat16 g_xl[(size_t)T_TOK * H_DIM];
__device__ __nv_bfloat16 g_wguh[(size_t)E_NUM * 2 * I_DIM * H_DIM];
__device__ __nv_bfloat16 g_wgul[(size_t)E_NUM * 2 * I_DIM * H_DIM];
__device__ __nv_bfloat16 g_wdh[(size_t)E_NUM * H_DIM * I_DIM];
__device__ __nv_bfloat16 g_wdl[(size_t)E_NUM * H_DIM * I_DIM];
__device__ __nv_bfloat16 g_acth[(size_t)A_TOT * I_DIM];
__device__ __nv_bfloat16 g_actl[(size_t)A_TOT * I_DIM];
__device__ float g_eo[(size_t)A_TOT * H_DIM];

// ---------------------------------------------------------------------------
// PTX helpers (base PTX, valid on sm_100 target)
// ---------------------------------------------------------------------------
__device__ __forceinline__ uint32_t smem_u32(const void* p) {
    uint32_t a;
    asm("{ .reg .u64 t; cvta.to.shared.u64 t, %1; cvt.u32.u64 %0, t; }" : "=r"(a) : "l"(p));
    return a;
}

#define LDSM_X4(R0, R1, R2, R3, ADDR) \
    asm volatile("ldmatrix.sync.aligned.m8n8.x4.shared.b16 {%0,%1,%2,%3}, [%4];" \
        : "=r"(R0), "=r"(R1), "=r"(R2), "=r"(R3) : "r"(ADDR))

#define MMA_BF16(D, A, B0, B1) \
    asm volatile("mma.sync.aligned.m16n8k16.row.col.f32.bf16.bf16.f32 " \
        "{%0,%1,%2,%3}, {%4,%5,%6,%7}, {%8,%9}, {%0,%1,%2,%3};" \
        : "+f"((D)[0]), "+f"((D)[1]), "+f"((D)[2]), "+f"((D)[3]) \
        : "r"((A)[0]), "r"((A)[1]), "r"((A)[2]), "r"((A)[3]), "r"(B0), "r"(B1))

#define CP_ASYNC16(DST, SRC, SZ) \
    asm volatile("cp.async.cg.shared.global [%0], [%1], 16, %2;" \
        :: "r"(DST), "l"(SRC), "r"(SZ))
#define CP_COMMIT  asm volatile("cp.async.commit_group;" ::: "memory")
#define CP_WAIT1   asm volatile("cp.async.wait_group 1;" ::: "memory")
#define CP_WAIT0   asm volatile("cp.async.wait_group 0;" ::: "memory")

// fp32x4 -> bf16 hi/lo packed pairs
__device__ __forceinline__ void split4(float4 v, uint2& uh, uint2& ul) {
    __nv_bfloat16 h0 = __float2bfloat16(v.x), h1 = __float2bfloat16(v.y);
    __nv_bfloat16 h2 = __float2bfloat16(v.z), h3 = __float2bfloat16(v.w);
    __nv_bfloat16 l0 = __float2bfloat16(v.x - __bfloat162float(h0));
    __nv_bfloat16 l1 = __float2bfloat16(v.y - __bfloat162float(h1));
    __nv_bfloat16 l2 = __float2bfloat16(v.z - __bfloat162float(h2));
    __nv_bfloat16 l3 = __float2bfloat16(v.w - __bfloat162float(h3));
    uh.x = (uint32_t)__bfloat16_as_ushort(h0) | ((uint32_t)__bfloat16_as_ushort(h1) << 16);
    uh.y = (uint32_t)__bfloat16_as_ushort(h2) | ((uint32_t)__bfloat16_as_ushort(h3) << 16);
    ul.x = (uint32_t)__bfloat16_as_ushort(l0) | ((uint32_t)__bfloat16_as_ushort(l1) << 16);
    ul.y = (uint32_t)__bfloat16_as_ushort(l2) | ((uint32_t)__bfloat16_as_ushort(l3) << 16);
}

// ---------------------------------------------------------------------------
// Conversion kernels: fp32 -> (hi, lo) bf16, grid-stride over float4s
// ---------------------------------------------------------------------------
__device__ __forceinline__ void conv_body(const float* __restrict__ src,
                                          __nv_bfloat16* __restrict__ hi,
                                          __nv_bfloat16* __restrict__ lo, int n4) {
    int i = blockIdx.x * blockDim.x + threadIdx.x;
    int stride = gridDim.x * blockDim.x;
    for (; i < n4; i += stride) {
        float4 v = ((const float4*)src)[i];
        uint2 uh, ul;
        split4(v, uh, ul);
        ((uint2*)hi)[i] = uh;
        ((uint2*)lo)[i] = ul;
    }
}
__global__ void conv_x(const float* __restrict__ s)   { conv_body(s, g_xh,   g_xl,   T_TOK * H_DIM / 4); }
__global__ void conv_wgu(const float* __restrict__ s) { conv_body(s, g_wguh, g_wgul, E_NUM * 2 * I_DIM * H_DIM / 4); }
__global__ void conv_wd(const float* __restrict__ s)  { conv_body(s, g_wdh,  g_wdl,  E_NUM * H_DIM * I_DIM / 4); }

// ---------------------------------------------------------------------------
// Routing: single block
// ---------------------------------------------------------------------------
__global__ void route_all(const int* __restrict__ topk) {
    __shared__ int cnt[E_NUM], cur[E_NUM];
    int tid = threadIdx.x;
    if (tid < E_NUM) cnt[tid] = 0;
    __syncthreads();
    for (int a = tid; a < A_TOT; a += blockDim.x) atomicAdd(&cnt[topk[a]], 1);
    __syncthreads();
    if (tid == 0) {
        int s = 0;
        for (int e = 0; e < E_NUM; e++) {
            g_count[e] = cnt[e];
            g_offset[e] = s;
            cur[e] = s;
            s += cnt[e];
        }
    }
    __syncthreads();
    for (int a = tid; a < A_TOT; a += blockDim.x) {
        int e = topk[a];
        int s = atomicAdd(&cur[e], 1);
        g_perm[s] = a;
        g_slot[a] = s;
    }
}

// ---------------------------------------------------------------------------
// SMEM layout: KC=32 bf16 cols padded to stride 40 (conflict-free ldmatrix)
// Per stage: Ah | Al | Bh | Bl tiles of 128 x KC
// ---------------------------------------------------------------------------
#define KC      32
#define STRIDE  40
#define TILE_E  (128 * STRIDE)        // 5120 elems
#define STAGE_E (4 * TILE_E)          // 20480 elems
#define SMEM_BYTES (2 * STAGE_E * 2)  // 81920 B

// Fragment loaders (mapping validated in round 3)
__device__ __forceinline__ void load_afrag(uint32_t sb, int eoff, int row0, int kk,
                                           int lane, uint32_t a[4]) {
    int row = row0 + (lane & 15);
    int col = kk + ((lane >> 4) << 3);
    uint32_t addr = sb + (uint32_t)(eoff + row * STRIDE + col) * 2;
    LDSM_X4(a[0], a[1], a[2], a[3], addr);
}
__device__ __forceinline__ void load_bfrag(uint32_t sb, int eoff, int nbase, int kk,
                                           int lane, uint32_t b[4]) {
    int row = nbase + (((lane >> 4) & 1) << 3) + (lane & 7);
    int col = kk + (((lane >> 3) & 1) << 3);
    uint32_t addr = sb + (uint32_t)(eoff + row * STRIDE + col) * 2;
    LDSM_X4(b[0], b[1], b[2], b[3], addr);
}

// ---------------------------------------------------------------------------
// GEMM1: act = silu(X*Wg^T) * (X*Wu^T).  Block 128 slots x 64 gate (+64 up).
// ---------------------------------------------------------------------------
#define NCH1 (H_DIM / KC)   // 32

__global__ __launch_bounds__(256, 2)
void gemm1(void) {
    const int e   = blockIdx.z;
    const int cnt = g_count[e];
    const int m0  = blockIdx.x * 128;
    if (m0 >= cnt) return;
    const int off  = g_offset[e];
    const int n0g  = blockIdx.y * 64;
    const int cntm = cnt - m0;

    extern __shared__ __nv_bfloat16 smem[];
    __shared__ int rowtok[128];
    const uint32_t sb = smem_u32(smem);

    const int tid = threadIdx.x, lane = tid & 31, wid = tid >> 5;
    const int wm = wid & 3, wn = wid >> 2;

    if (tid < 128)
        rowtok[tid] = (tid < cntm) ? g_perm[off + m0 + tid] / K_TOP : -1;
    __syncthreads();

    const __nv_bfloat16* wh = g_wguh + (size_t)e * (2 * I_DIM) * H_DIM;
    const __nv_bfloat16* wl = g_wgul + (size_t)e * (2 * I_DIM) * H_DIM;

    // issue one stage of cp.async (2048 x 16B)
    auto issue = [&](int k0, int soE) {
        #pragma unroll
        for (int i = 0; i < 8; i++) {
            int idx = tid + i * 256;
            int seg = idx & 3;
            int row = (idx >> 2) & 127;
            int mat = idx >> 9;                  // 0=Ah 1=Al 2=Bh 3=Bl
            uint32_t dst = sb + (uint32_t)(soE + mat * TILE_E + row * STRIDE + seg * 8) * 2;
            const __nv_bfloat16* src;
            uint32_t sz = 16;
            if (mat < 2) {
                int tok = rowtok[row];
                const __nv_bfloat16* base = mat ? g_xl : g_xh;
                src = base + (size_t)(tok < 0 ? 0 : tok) * H_DIM + k0 + seg * 8;
                if (tok < 0) sz = 0;
            } else {
                int wr = (row < 64) ? (n0g + row) : (I_DIM + n0g + row - 64);
                const __nv_bfloat16* base = (mat == 2) ? wh : wl;
                src = base + (size_t)wr * H_DIM + k0 + seg * 8;
            }
            CP_ASYNC16(dst, src, sz);
        }
        CP_COMMIT;
    };

    float accG[2][4][4], accU[2][4][4];
    #pragma unroll
    for (int a = 0; a < 2; a++)
        #pragma unroll
        for (int b = 0; b < 4; b++)
            #pragma unroll
            for (int c = 0; c < 4; c++) { accG[a][b][c] = 0.f; accU[a][b][c] = 0.f; }

    issue(0, 0);

    for (int c = 0; c < NCH1; c++) {
        const int s = c & 1;
        if (c + 1 < NCH1) { issue((c + 1) * KC, (s ^ 1) * STAGE_E); CP_WAIT1; }
        else CP_WAIT0;
        __syncthreads();

        const int so = s * STAGE_E;
        #pragma unroll
        for (int kk = 0; kk < KC; kk += 16) {
            uint32_t ah[2][4], al[2][4];
            #pragma unroll
            for (int mt = 0; mt < 2; mt++) {
                load_afrag(sb, so + 0 * TILE_E, wm * 32 + mt * 16, kk, lane, ah[mt]);
                load_afrag(sb, so + 1 * TILE_E, wm * 32 + mt * 16, kk, lane, al[mt]);
            }
            #pragma unroll
            for (int p = 0; p < 2; p++) {
                const int nbg = wn * 32 + p * 16;
                uint32_t bgh[4], bgl[4], buh[4], bul[4];
                load_bfrag(sb, so + 2 * TILE_E, nbg,      kk, lane, bgh);
                load_bfrag(sb, so + 3 * TILE_E, nbg,      kk, lane, bgl);
                load_bfrag(sb, so + 2 * TILE_E, nbg + 64, kk, lane, buh);
                load_bfrag(sb, so + 3 * TILE_E, nbg + 64, kk, lane, bul);
                #pragma unroll
                for (int mt = 0; mt < 2; mt++) {
                    #pragma unroll
                    for (int q = 0; q < 2; q++) {
                        float* dG = accG[mt][2 * p + q];
                        float* dU = accU[mt][2 * p + q];
                        MMA_BF16(dG, ah[mt], bgh[2 * q], bgh[2 * q + 1]);
                        MMA_BF16(dG, ah[mt], bgl[2 * q], bgl[2 * q + 1]);
                        MMA_BF16(dG, al[mt], bgh[2 * q], bgh[2 * q + 1]);
                        MMA_BF16(dU, ah[mt], buh[2 * q], buh[2 * q + 1]);
                        MMA_BF16(dU, ah[mt], bul[2 * q], bul[2 * q + 1]);
                        MMA_BF16(dU, al[mt], buh[2 * q], buh[2 * q + 1]);
                    }
                }
            }
        }
        __syncthreads();
    }

    // epilogue: silu(gate)*up -> bf16 hi/lo act arrays
    const int gid = lane >> 2, tig = lane & 3;
    #pragma unroll
    for (int mt = 0; mt < 2; mt++) {
        #pragma unroll
        for (int nt = 0; nt < 4; nt++) {
            int colg = n0g + wn * 32 + nt * 8 + 2 * tig;
            #pragma unroll
            for (int h = 0; h < 2; h++) {
                int rowl = wm * 32 + mt * 16 + gid + h * 8;
                if (rowl < cntm) {
                    float g0 = accG[mt][nt][2 * h],     u0 = accU[mt][nt][2 * h];
                    float g1 = accG[mt][nt][2 * h + 1], u1 = accU[mt][nt][2 * h + 1];
                    float v0 = (g0 / (1.f + __expf(-g0))) * u0;
                    float v1 = (g1 / (1.f + __expf(-g1))) * u1;
                    __nv_bfloat16 h0 = __float2bfloat16(v0);
                    __nv_bfloat16 h1 = __float2bfloat16(v1);
                    __nv_bfloat16 l0 = __float2bfloat16(v0 - __bfloat162float(h0));
                    __nv_bfloat16 l1 = __float2bfloat16(v1 - __bfloat162float(h1));
                    size_t o = (size_t)(off + m0 + rowl) * I_DIM + colg;
                    *(uint32_t*)(g_acth + o) =
                        (uint32_t)__bfloat16_as_ushort(h0) | ((uint32_t)__bfloat16_as_ushort(h1) << 16);
                    *(uint32_t*)(g_actl + o) =
                        (uint32_t)__bfloat16_as_ushort(l0) | ((uint32_t)__bfloat16_as_ushort(l1) << 16);
                }
            }
        }
    }
}

// ---------------------------------------------------------------------------
// GEMM2: eo = act * Wd^T.  Block 128 slots x 128 H cols, K = 768.
// ---------------------------------------------------------------------------
#define NCH2 (I_DIM / KC)   // 24

__global__ __launch_bounds__(256, 2)
void gemm2(void) {
    const int e   = blockIdx.z;
    const int cnt = g_count[e];
    const int m0  = blockIdx.x * 128;
    if (m0 >= cnt) return;
    const int off  = g_offset[e];
    const int n0   = blockIdx.y * 128;
    const int cntm = cnt - m0;

    extern __shared__ __nv_bfloat16 smem[];
    const uint32_t sb = smem_u32(smem);

    const int tid = threadIdx.x, lane = tid & 31, wid = tid >> 5;
    const int wm = wid & 3, wn = wid >> 2;

    const __nv_bfloat16* wh = g_wdh + (size_t)e * H_DIM * I_DIM;
    const __nv_bfloat16* wl = g_wdl + (size_t)e * H_DIM * I_DIM;

    auto issue = [&](int k0, int soE) {
        #pragma unroll
        for (int i = 0; i < 8; i++) {
            int idx = tid + i * 256;
            int seg = idx & 3;
            int row = (idx >> 2) & 127;
            int mat = idx >> 9;
            uint32_t dst = sb + (uint32_t)(soE + mat * TILE_E + row * STRIDE + seg * 8) * 2;
            const __nv_bfloat16* src;
            uint32_t sz = 16;
            if (mat < 2) {
                const __nv_bfloat16* base = mat ? g_actl : g_acth;
                int r = (row < cntm) ? row : 0;
                src = base + (size_t)(off + m0 + r) * I_DIM + k0 + seg * 8;
                if (row >= cntm) sz = 0;
            } else {
                const __nv_bfloat16* base = (mat == 2) ? wh : wl;
                src = base + (size_t)(n0 + row) * I_DIM + k0 + seg * 8;
            }
            CP_ASYNC16(dst, src, sz);
        }
        CP_COMMIT;
    };

    float acc[2][8][4];
    #pragma unroll
    for (int a = 0; a < 2; a++)
        #pragma unroll
        for (int b = 0; b < 8; b++)
            #pragma unroll
            for (int c = 0; c < 4; c++) acc[a][b][c] = 0.f;

    issue(0, 0);

    for (int c = 0; c < NCH2; c++) {
        const int s = c & 1;
        if (c + 1 < NCH2) { issue((c + 1) * KC, (s ^ 1) * STAGE_E); CP_WAIT1; }
        else CP_WAIT0;
        __syncthreads();

        const int so = s * STAGE_E;
        #pragma unroll
        for (int kk = 0; kk < KC; kk += 16) {
            uint32_t ah[2][4], al[2][4];
            #pragma unroll
            for (int mt = 0; mt < 2; mt++) {
                load_afrag(sb, so + 0 * TILE_E, wm * 32 + mt * 16, kk, lane, ah[mt]);
                load_afrag(sb, so + 1 * TILE_E, wm * 32 + mt * 16, kk, lane, al[mt]);
            }
            #pragma unroll
            for (int p = 0; p < 4; p++) {
                const int nb = wn * 64 + p * 16;
                uint32_t bh[4], bl[4];
                load_bfrag(sb, so + 2 * TILE_E, nb, kk, lane, bh);
                load_bfrag(sb, so + 3 * TILE_E, nb, kk, lane, bl);
                #pragma unroll
                for (int mt = 0; mt < 2; mt++) {
                    #pragma unroll
                    for (int q = 0; q < 2; q++) {
                        float* d = acc[mt][2 * p + q];
                        MMA_BF16(d, ah[mt], bh[2 * q], bh[2 * q + 1]);
                        MMA_BF16(d, ah[mt], bl[2 * q], bl[2 * q + 1]);
                        MMA_BF16(d, al[mt], bh[2 * q], bh[2 * q + 1]);
                    }
                }
            }
        }
        __syncthreads();
    }

    const int gid = lane >> 2, tig = lane & 3;
    #pragma unroll
    for (int mt = 0; mt < 2; mt++) {
        #pragma unroll
        for (int nt = 0; nt < 8; nt++) {
            int col = n0 + wn * 64 + nt * 8 + 2 * tig;
            #pragma unroll
            for (int h = 0; h < 2; h++) {
                int rowl = wm * 32 + mt * 16 + gid + h * 8;
                if (rowl < cntm) {
                    float2 r = make_float2(acc[mt][nt][2 * h], acc[mt][nt][2 * h + 1]);
                    *(float2*)(g_eo + (size_t)(off + m0 + rowl) * H_DIM + col) = r;
                }
            }
        }
    }
}

// ---------------------------------------------------------------------------
// Combine
// ---------------------------------------------------------------------------
__global__ void combine(const float* __restrict__ wts, float* __restrict__ out) {
    int idx = blockIdx.x * blockDim.x + threadIdx.x;
    if (idx >= T_TOK * H_DIM / 4) return;
    int t  = idx / (H_DIM / 4);
    int h4 = idx % (H_DIM / 4);
    float w0 = wts[t * K_TOP + 0];
    float w1 = wts[t * K_TOP + 1];
    int s0 = g_slot[t * K_TOP + 0];
    int s1 = g_slot[t * K_TOP + 1];
    float4 a = ((const float4*)(g_eo + (size_t)s0 * H_DIM))[h4];
    float4 b = ((const float4*)(g_eo + (size_t)s1 * H_DIM))[h4];
    float4 r;
    r.x = w0 * a.x + w1 * b.x;
    r.y = w0 * a.y + w1 * b.y;
    r.z = w0 * a.z + w1 * b.z;
    r.w = w0 * a.w + w1 * b.w;
    ((float4*)out)[idx] = r;
}

// ---------------------------------------------------------------------------
// Launch
// ---------------------------------------------------------------------------
extern "C" void kernel_launch(void* const* d_in, const int* in_sizes, int n_in,
                              void* d_out, int out_size) {
    const float* X    = (const float*)d_in[0];
    const float* Wgu  = (const float*)d_in[1];
    const float* Wd   = (const float*)d_in[2];
    const int*   topk = (const int*)  d_in[3];
    const float* wts  = (const float*)d_in[4];
    float*       out  = (float*)d_out;

    cudaFuncSetAttribute(gemm1, cudaFuncAttributeMaxDynamicSharedMemorySize, SMEM_BYTES);
    cudaFuncSetAttribute(gemm2, cudaFuncAttributeMaxDynamicSharedMemorySize, SMEM_BYTES);

    route_all<<<1, 1024>>>(topk);
    conv_x  <<<512, 256>>>(X);
    conv_wgu<<<2048, 256>>>(Wgu);
    conv_wd <<<1024, 256>>>(Wd);

    dim3 g1(A_TOT / 128, I_DIM / 64, E_NUM);    // (32, 12, 8)
    gemm1<<<g1, 256, SMEM_BYTES>>>();

    dim3 g2(A_TOT / 128, H_DIM / 128, E_NUM);   // (32, 8, 8)
    gemm2<<<g2, 256, SMEM_BYTES>>>();

    combine<<<(T_TOK * H_DIM / 4 + 255) / 256, 256>>>(wts, out);
}